// round 10
// baseline (speedup 1.0000x reference)
#include <cuda_runtime.h>
#include <cstdint>

// Problem constants (fixed by the reference):
//   NUM_BLOCKS=8192, BLOCK_SIZE=16, NUM_HEADS=8, HEAD_SIZE=128
//   NUM_TOKENS=65536, NUM_SLOTS = 8192*16 = 131072
//   per-slot payload = 8*128 fp32 = 1024 floats = 4096 bytes = 256 float4
#define NUM_SLOTS       131072
#define NUM_TOKENS      65536
#define VEC4_PER_SLOT   256
#define SLOTS_PER_GROUP 4
#define NUM_GROUPS      (NUM_SLOTS / SLOTS_PER_GROUP)   // 32768
#define GRID            1184                             // 148 SMs x 8 CTAs, all co-resident
#define THREADS         256

// Inverse slot map, encoded token+1 (0 = slot untouched).
// INVARIANT: all-zero at entry (zero-init at load; phase 2 restores every
// entry it consumes to zero, so every call sees identical initial state).
__device__ int g_inv_map[NUM_SLOTS];

// Grid barrier state. INVARIANT: all-zero at entry; the last CTA through
// g_done resets everything, so each call is identical.
__device__ unsigned g_arrive;
__device__ volatile unsigned g_release;
__device__ unsigned g_done;

__global__ void __launch_bounds__(THREADS, 8) fused_cache_kernel(
    const int4*   __restrict__ slot_mapping,   // [NUM_TOKENS] as int4
    const float4* __restrict__ to_cache,
    const float4* __restrict__ kv_cache,
    float4*       __restrict__ out)
{
    const unsigned tid  = threadIdx.x;
    const unsigned gtid = blockIdx.x * THREADS + tid;

    // ── Phase 1: scatter inverse map (first 16384 threads, 4 tokens each) ──
    if (gtid < NUM_TOKENS / 4) {
        const int4 s = slot_mapping[gtid];
        const int base = 4 * (int)gtid + 1;      // token+1 encoding
        g_inv_map[s.x] = base + 0;
        g_inv_map[s.y] = base + 1;
        g_inv_map[s.z] = base + 2;
        g_inv_map[s.w] = base + 3;
    }

    // ── Grid barrier: all map writes visible before any map read ──
    __syncthreads();
    if (tid == 0) {
        __threadfence();
        unsigned v = atomicAdd(&g_arrive, 1u);
        if (v + 1 == GRID) g_release = 1u;
        while (g_release == 0u) __nanosleep(64);
        __threadfence();   // acquire: order map reads after release observation
    }
    __syncthreads();

    // ── Phase 2: persistent merge loop ──
    for (unsigned g = blockIdx.x; g < NUM_GROUPS; g += GRID) {
        const unsigned slot_base = g * SLOTS_PER_GROUP;

        // All 4 map entries in one 16B broadcast load.
        const int4 m = *(const int4*)&g_inv_map[slot_base];
        const int srcs[SLOTS_PER_GROUP] = { m.x, m.y, m.z, m.w };

        const float4* srcp[SLOTS_PER_GROUP];
#pragma unroll
        for (int s = 0; s < SLOTS_PER_GROUP; s++) {
            const unsigned slot = slot_base + s;
            srcp[s] = (srcs[s] > 0)
                    ? (to_cache + (size_t)(srcs[s] - 1) * VEC4_PER_SLOT)
                    : (kv_cache + (size_t)slot * VEC4_PER_SLOT);
        }

        // Front-batch 4 independent 16B loads (MLP=4); they stay in flight
        // across the barrier (BAR waits on arrival, not LDG completion).
        float4 v[SLOTS_PER_GROUP];
#pragma unroll
        for (int s = 0; s < SLOTS_PER_GROUP; s++)
            v[s] = __ldcs(srcp[s] + tid);

        // All warps have read this group's map entries; restore them to zero.
        __syncthreads();
        if (tid == 0)
            *(int4*)&g_inv_map[slot_base] = make_int4(0, 0, 0, 0);

#pragma unroll
        for (int s = 0; s < SLOTS_PER_GROUP; s++)
            __stcs(out + (size_t)(slot_base + s) * VEC4_PER_SLOT + tid, v[s]);
    }

    // ── Barrier-state reset by the last CTA to finish ──
    __syncthreads();
    if (tid == 0) {
        unsigned v = atomicAdd(&g_done, 1u);
        if (v + 1 == GRID) {
            g_arrive  = 0u;
            g_release = 0u;
            g_done    = 0u;
            __threadfence();
        }
    }
}

extern "C" void kernel_launch(void* const* d_in, const int* in_sizes, int n_in,
                              void* d_out, int out_size)
{
    const float4* to_cache     = (const float4*)d_in[0];  // [65536, 8, 128] f32
    const float4* kv_cache     = (const float4*)d_in[1];  // [8192, 16, 8, 128] f32
    const int4*   slot_mapping = (const int4*)d_in[2];    // [65536] i32, as int4
    float4*       out          = (float4*)d_out;          // full updated kv_cache

    fused_cache_kernel<<<GRID, THREADS>>>(slot_mapping, to_cache, kv_cache, out);
}

// round 12
// speedup vs baseline: 1.2523x; 1.2523x over previous
#include <cuda_runtime.h>
#include <cstdint>

// Problem constants (fixed by the reference):
//   NUM_BLOCKS=8192, BLOCK_SIZE=16, NUM_HEADS=8, HEAD_SIZE=128
//   NUM_TOKENS=65536, NUM_SLOTS = 8192*16 = 131072
//   per-slot payload = 8*128 fp32 = 1024 floats = 4096 bytes = 256 float4
#define NUM_SLOTS       131072
#define NUM_TOKENS      65536
#define VEC4_PER_SLOT   256
#define SLOTS_PER_BLOCK 4

// Inverse slot map, encoded token+1 (0 = slot untouched).
// INVARIANT: all-zero at entry to kernel_launch. Zero-initialized at module
// load; the merge kernel restores every entry it consumes back to zero, so
// every call sees the same initial state and does identical work.
__device__ int g_inv_map[NUM_SLOTS];

// 4 tokens per thread via one int4 load; 4 scattered 4B stores each.
__global__ void __launch_bounds__(512) scatter_inv_map_kernel(
    const int4* __restrict__ slot_mapping)
{
    int i = blockIdx.x * blockDim.x + threadIdx.x;   // i in [0, NUM_TOKENS/4)
    const int4 s = slot_mapping[i];
    const int base = 4 * i + 1;                      // token+1 encoding
    g_inv_map[s.x] = base + 0;
    g_inv_map[s.y] = base + 1;
    g_inv_map[s.z] = base + 2;
    g_inv_map[s.w] = base + 3;
}

// One block per 4 consecutive slots; 256 threads each move float4 #t of each
// of the 4 slots. 4 independent 16B loads front-batched per thread (MLP=4),
// fully coalesced, regs 24-28 -> occ ~84%. Streaming hints: zero reuse.
// After reading its 4 map entries (single int4 broadcast), the block restores
// them to zero (thread 0, behind a barrier) to maintain the invariant.
// Latency hiding comes from grid depth (32768 independent CTAs), which R10
// showed is strictly better than a persistent loop for this pattern.
__global__ void __launch_bounds__(256, 8) merge_write_kernel(
    const float4* __restrict__ to_cache,
    const float4* __restrict__ kv_cache,
    float4* __restrict__ out)
{
    const unsigned slot_base = blockIdx.x * SLOTS_PER_BLOCK;
    const unsigned t = threadIdx.x;

    // All 4 map entries in one 16B broadcast load.
    const int4 m = *(const int4*)&g_inv_map[slot_base];
    const int srcs[SLOTS_PER_BLOCK] = { m.x, m.y, m.z, m.w };

    const float4* srcp[SLOTS_PER_BLOCK];
#pragma unroll
    for (int s = 0; s < SLOTS_PER_BLOCK; s++) {
        const unsigned slot = slot_base + s;
        srcp[s] = (srcs[s] > 0) ? (to_cache + (size_t)(srcs[s] - 1) * VEC4_PER_SLOT)
                                : (kv_cache + (size_t)slot * VEC4_PER_SLOT);
    }

    // Front-batch the 4 independent payload loads (in flight across the barrier).
    float4 v[SLOTS_PER_BLOCK];
#pragma unroll
    for (int s = 0; s < SLOTS_PER_BLOCK; s++)
        v[s] = __ldcs(srcp[s] + t);

    // All warps have read the map entries; now it is safe to clear them.
    __syncthreads();
    if (t == 0)
        *(int4*)&g_inv_map[slot_base] = make_int4(0, 0, 0, 0);

#pragma unroll
    for (int s = 0; s < SLOTS_PER_BLOCK; s++)
        __stcs(out + (size_t)(slot_base + s) * VEC4_PER_SLOT + t, v[s]);
}

extern "C" void kernel_launch(void* const* d_in, const int* in_sizes, int n_in,
                              void* d_out, int out_size)
{
    const float4* to_cache     = (const float4*)d_in[0];  // [65536, 8, 128] f32
    const float4* kv_cache     = (const float4*)d_in[1];  // [8192, 16, 8, 128] f32
    const int4*   slot_mapping = (const int4*)d_in[2];    // [65536] i32, as int4
    float4*       out          = (float4*)d_out;          // full updated kv_cache

    scatter_inv_map_kernel<<<NUM_TOKENS / 4 / 512, 512>>>(slot_mapping);
    merge_write_kernel<<<NUM_SLOTS / SLOTS_PER_BLOCK, 256>>>(to_cache, kv_cache, out);
}

// round 14
// speedup vs baseline: 1.2528x; 1.0004x over previous
#include <cuda_runtime.h>
#include <cstdint>

// Problem constants (fixed by the reference):
//   NUM_BLOCKS=8192, BLOCK_SIZE=16, NUM_HEADS=8, HEAD_SIZE=128
//   NUM_TOKENS=65536, NUM_SLOTS = 8192*16 = 131072
//   per-slot payload = 8*128 fp32 = 1024 floats = 4096 bytes = 256 float4
#define NUM_SLOTS       131072
#define NUM_TOKENS      65536
#define VEC4_PER_SLOT   256
#define SLOTS_PER_BLOCK 4

// Inverse slot map, encoded token+1 (0 = slot untouched).
// INVARIANT: all-zero at entry to kernel_launch. Zero-initialized at module
// load; the merge kernel restores every entry it consumes back to zero, so
// every call sees the same initial state and does identical work.
__device__ int g_inv_map[NUM_SLOTS];

// One token per thread: one coalesced 4B load + one scattered 4B store.
// Maximum store-level parallelism, single-STG critical path per thread.
__global__ void __launch_bounds__(512) scatter_inv_map_kernel(
    const int* __restrict__ slot_mapping)
{
    int i = blockIdx.x * blockDim.x + threadIdx.x;   // i in [0, NUM_TOKENS)
    g_inv_map[slot_mapping[i]] = i + 1;              // token+1 encoding
}

// One block per 4 consecutive slots; 256 threads each move float4 #t of each
// of the 4 slots. 4 independent 16B loads front-batched per thread (MLP=4),
// fully coalesced, regs ~28 -> occ ~84%. Streaming hints: zero reuse.
// After reading its 4 map entries (single int4 broadcast), the block restores
// them to zero (thread 0, behind a barrier) to maintain the invariant.
// Latency hiding comes from grid depth (32768 independent CTAs), which R10
// showed is strictly better than a persistent loop for this pattern.
__global__ void __launch_bounds__(256, 8) merge_write_kernel(
    const float4* __restrict__ to_cache,
    const float4* __restrict__ kv_cache,
    float4* __restrict__ out)
{
    const unsigned slot_base = blockIdx.x * SLOTS_PER_BLOCK;
    const unsigned t = threadIdx.x;

    // All 4 map entries in one 16B broadcast load.
    const int4 m = *(const int4*)&g_inv_map[slot_base];
    const int srcs[SLOTS_PER_BLOCK] = { m.x, m.y, m.z, m.w };

    const float4* srcp[SLOTS_PER_BLOCK];
#pragma unroll
    for (int s = 0; s < SLOTS_PER_BLOCK; s++) {
        const unsigned slot = slot_base + s;
        srcp[s] = (srcs[s] > 0) ? (to_cache + (size_t)(srcs[s] - 1) * VEC4_PER_SLOT)
                                : (kv_cache + (size_t)slot * VEC4_PER_SLOT);
    }

    // Front-batch the 4 independent payload loads (in flight across the barrier).
    float4 v[SLOTS_PER_BLOCK];
#pragma unroll
    for (int s = 0; s < SLOTS_PER_BLOCK; s++)
        v[s] = __ldcs(srcp[s] + t);

    // All warps have read the map entries; now it is safe to clear them.
    __syncthreads();
    if (t == 0)
        *(int4*)&g_inv_map[slot_base] = make_int4(0, 0, 0, 0);

#pragma unroll
    for (int s = 0; s < SLOTS_PER_BLOCK; s++)
        __stcs(out + (size_t)(slot_base + s) * VEC4_PER_SLOT + t, v[s]);
}

extern "C" void kernel_launch(void* const* d_in, const int* in_sizes, int n_in,
                              void* d_out, int out_size)
{
    const float4* to_cache     = (const float4*)d_in[0];  // [65536, 8, 128] f32
    const float4* kv_cache     = (const float4*)d_in[1];  // [8192, 16, 8, 128] f32
    const int*    slot_mapping = (const int*)d_in[2];     // [65536] i32
    float4*       out          = (float4*)d_out;          // full updated kv_cache

    scatter_inv_map_kernel<<<NUM_TOKENS / 512, 512>>>(slot_mapping);
    merge_write_kernel<<<NUM_SLOTS / SLOTS_PER_BLOCK, 256>>>(to_cache, kv_cache, out);
}